// round 11
// baseline (speedup 1.0000x reference)
#include <cuda_runtime.h>
#include <cuda_bf16.h>

#define FULLMASK 0xFFFFFFFFu
#define LOG2E 1.4426950408889634f

using u64 = unsigned long long;

__device__ __forceinline__ u64 fma2(u64 a, u64 b, u64 c) {
    u64 d; asm("fma.rn.f32x2 %0,%1,%2,%3;" : "=l"(d) : "l"(a), "l"(b), "l"(c)); return d;
}
__device__ __forceinline__ u64 add2(u64 a, u64 b) {
    u64 d; asm("add.rn.f32x2 %0,%1,%2;" : "=l"(d) : "l"(a), "l"(b)); return d;
}
__device__ __forceinline__ u64 bcast2(float v) {
    u64 d; asm("mov.b64 %0,{%1,%1};" : "=l"(d) : "f"(v)); return d;
}
__device__ __forceinline__ float2 unpk(u64 v) {
    float2 r; asm("mov.b64 {%0,%1},%2;" : "=f"(r.x), "=f"(r.y) : "l"(v)); return r;
}
__device__ __forceinline__ float ex2f(float x) {
    float r; asm("ex2.approx.f32 %0,%1;" : "=f"(r) : "f"(x)); return r;
}
__device__ __forceinline__ float rcpf(float x) {
    float r; asm("rcp.approx.f32 %0,%1;" : "=f"(r) : "f"(x)); return r;
}
__device__ __forceinline__ float rsqf(float x) {
    float r; asm("rsqrt.approx.f32 %0,%1;" : "=f"(r) : "f"(x)); return r;
}

union Row { ulonglong2 u; float4 f; };

#define N_WARPS 4
#define STAGE_UNITS 260   // 256 tile units (16B) + 4 pad (u>>6 skew)

// Persistent warps + per-warp 2-stage cp.async pipeline.
//
// Compute layout (R7, proven): 4 locations/warp-tile, 8 lanes/location.
// t=lane&7, h=t>>2 (row-half), q=t&3 (d-quad). Lane holds 8 rows of its half
// in ROTATION ORDER: slot (k,j) -> row 2*((q+k)&3)+j, cols 4q..4q+3.
// Lane OWNS rows 8h+2q,8h+2q+1 (logits bb0/bb1, exponentials). Quad comm via
// width-4 shfl.idx, compile-time slots; agree = ring reduce.
// b in log2-space; softmax 1/s cancels inside squash:
//   out = a*sq*rcp(s^2+sq)*rsq(sq+eps*s^2).  No max-subtract.
//
// Data feed: LDGSTS (cp.async.cg, 16B/lane, 512B coalesced rounds) stages each
// 4KB tile into smem; warp computes tile t from stage while t+2's loads are in
// flight -> continuous DRAM issue, tile-start stall = LDS(29cy) not LDG(600cy).
__global__ void __launch_bounds__(128) routing_kernel(
    const float* __restrict__ pred,
    const float* __restrict__ b_in,
    const int*   __restrict__ nit,
    float*       __restrict__ out,
    int n_tiles, int ohw, int ohw_mask, unsigned stride)
{
    __shared__ __align__(16) float4 sm[N_WARPS][2][STAGE_UNITS];

    const int lane  = threadIdx.x & 31;
    const int wslot = threadIdx.x >> 5;
    const int t = lane & 7;
    const int h = t >> 2;
    const int q = t & 3;
    const int g = lane >> 3;
    const int s1 = (q + 1) & 3, s2 = (q + 2) & 3, s3 = (q + 3) & 3;

    unsigned w = blockIdx.x * N_WARPS + wslot;
    if (w >= (unsigned)n_tiles) return;

    const int iters = *nit;

    auto prefetch = [&](unsigned wi, int st) {
        if (wi < (unsigned)n_tiles) {
            const char* src = (const char*)pred + (size_t)wi * 4096;
#pragma unroll
            for (int r = 0; r < 8; ++r) {
                const unsigned u  = 32u * r + (unsigned)lane;   // linear unit
                const unsigned du = u + (u >> 6);               // skewed dest
                const unsigned daddr =
                    (unsigned)__cvta_generic_to_shared(&sm[wslot][st][du]);
                asm volatile("cp.async.cg.shared.global [%0], [%1], 16;\n"
                             :: "r"(daddr), "l"(src + 16 * u));
            }
        }
        asm volatile("cp.async.commit_group;\n" ::: "memory");
    };

    prefetch(w, 0);
    prefetch(w + stride, 1);

    int stage = 0;
    for (;;) {
        // b logits for this tile: issue LDG before the wait (overlaps)
        const unsigned loc  = w * 4u + g;
        const unsigned bloc = ohw_mask ? (loc & (unsigned)ohw_mask)
                                       : (loc % (unsigned)ohw);
        const float2 b2 = *reinterpret_cast<const float2*>(
            b_in + (size_t)bloc * 16 + 8 * h + 2 * q);

        asm volatile("cp.async.wait_group 1;\n" ::: "memory");
        __syncwarp();

        // tile -> registers (rotation order), skewed smem addressing
        Row P[8];
        {
            const float4* base = &sm[wslot][stage][0];
            const int lb = 65 * g + 32 * h + q;   // 64g+32h+q + skew(g)
#pragma unroll
            for (int k = 0; k < 4; ++k) {
                const int off = 8 * ((q + k) & 3);
                P[2 * k].f     = base[lb + off];
                P[2 * k + 1].f = base[lb + off + 4];
            }
        }
        __syncwarp();                      // all lanes done reading the stage
        prefetch(w + 2u * stride, stage);  // overwrite it with tile t+2

        float bb0 = b2.x * LOG2E, bb1 = b2.y * LOG2E;
        float o0, o1, o2, o3;

        auto pass = [&]() {
            const float e0 = ex2f(bb0), e1 = ex2f(bb1);
            float e[8];
            e[0] = e0; e[1] = e1;
            e[2] = __shfl_sync(FULLMASK, e0, s1, 4);
            e[3] = __shfl_sync(FULLMASK, e1, s1, 4);
            e[4] = __shfl_sync(FULLMASK, e0, s2, 4);
            e[5] = __shfl_sync(FULLMASK, e1, s2, 4);
            e[6] = __shfl_sync(FULLMASK, e0, s3, 4);
            e[7] = __shfl_sync(FULLMASK, e1, s3, 4);

            float s = ((e[0] + e[1]) + (e[2] + e[3])) +
                      ((e[4] + e[5]) + (e[6] + e[7]));
            s += __shfl_xor_sync(FULLMASK, s, 4);

            u64 x01 = 0ull, y01 = 0ull, x23 = 0ull, y23 = 0ull;
#pragma unroll
            for (int r = 0; r < 8; r += 2) {
                const u64 ea = bcast2(e[r]);
                const u64 eb = bcast2(e[r + 1]);
                x01 = fma2(ea, P[r].u.x, x01);
                x23 = fma2(ea, P[r].u.y, x23);
                y01 = fma2(eb, P[r + 1].u.x, y01);
                y23 = fma2(eb, P[r + 1].u.y, y23);
            }
            u64 a01 = add2(x01, y01);
            u64 a23 = add2(x23, y23);
            a01 = add2(a01, __shfl_xor_sync(FULLMASK, a01, 4));
            a23 = add2(a23, __shfl_xor_sync(FULLMASK, a23, 4));

            float2 lo = unpk(a01), hi = unpk(a23);
            const float a0 = lo.x, a1 = lo.y, a2 = hi.x, a3 = hi.y;

            float sq = fmaf(a3, a3, fmaf(a2, a2, fmaf(a1, a1, a0 * a0)));
            sq += __shfl_xor_sync(FULLMASK, sq, 1);
            sq += __shfl_xor_sync(FULLMASK, sq, 2);

            const float ssq = s * s;
            const float f   = sq * rcpf(ssq + sq) * rsqf(fmaf(1e-7f, ssq, sq));
            o0 = a0 * f; o1 = a1 * f; o2 = a2 * f; o3 = a3 * f;
        };

        pass();
        for (int it = 0; it < iters; ++it) {
            float pp[8];
#pragma unroll
            for (int m = 0; m < 8; ++m)
                pp[m] = fmaf(P[m].f.w, o3,
                        fmaf(P[m].f.z, o2,
                        fmaf(P[m].f.y, o1, P[m].f.x * o0)));
            const float r10 = __shfl_sync(FULLMASK, pp[6], s1, 4);
            const float r11 = __shfl_sync(FULLMASK, pp[7], s1, 4);
            const float r20 = __shfl_sync(FULLMASK, pp[4], s2, 4);
            const float r21 = __shfl_sync(FULLMASK, pp[5], s2, 4);
            const float r30 = __shfl_sync(FULLMASK, pp[2], s3, 4);
            const float r31 = __shfl_sync(FULLMASK, pp[3], s3, 4);
            const float p0 = (pp[0] + r10) + (r20 + r30);
            const float p1 = (pp[1] + r11) + (r21 + r31);

            bb0 = fmaf(p0, LOG2E, bb0);
            bb1 = fmaf(p1, LOG2E, bb1);
            pass();
        }

        if (h == 0)
            reinterpret_cast<float4*>(out)[(size_t)loc * 4 + q] =
                make_float4(o0, o1, o2, o3);

        w += stride;
        if (w >= (unsigned)n_tiles) break;
        stage ^= 1;
    }
}

extern "C" void kernel_launch(void* const* d_in, const int* in_sizes, int n_in,
                              void* d_out, int out_size) {
    const float* pred = (const float*)d_in[0];
    const float* b    = (const float*)d_in[1];
    const int*   nit  = (const int*)d_in[2];
    float* out = (float*)d_out;

    const int n_loc = in_sizes[0] / 256;   // B*O*H*W
    const int ohw   = in_sizes[1] / 16;    // O*H*W
    const int ohw_mask = ((ohw & (ohw - 1)) == 0) ? (ohw - 1) : 0;

    const int n_tiles = (n_loc + 3) / 4;   // 4 locations per warp-tile
    const int blocks  = 6 * 148;           // 6 resident 128-thread blocks/SM
    const unsigned stride = (unsigned)blocks * N_WARPS;
    routing_kernel<<<blocks, 128>>>(pred, b, nit, out,
                                    n_tiles, ohw, ohw_mask, stride);
}